// round 5
// baseline (speedup 1.0000x reference)
#include <cuda_runtime.h>

// Problem constants (fixed by the reference)
#define E_EDGES   2000000
#define NSEG      100000
#define INV_TEMP  0.125f   // 1 / TEMPERATURE

// Scratch (no allocs allowed): denominators + reciprocals.
// g_sum is zero-initialized at module load; rcp_kernel re-zeroes it every
// call, so each kernel_launch sees zeros -> deterministic across replays.
__device__ float g_sum[NSEG];
__device__ float g_rcp[NSEG];

// ---------------------------------------------------------------------------
// Index dtype detection: reference asks int64 but default JAX canonicalizes to
// int32. Probe 8 bytes at int64-position E/4: sorted uniform over [0,100000)
// -> int64 hi-word there is 0; int32 interpretation puts ~50000 there.
// ---------------------------------------------------------------------------
__device__ __forceinline__ bool index_is_64(const void* __restrict__ idx) {
    const int2 probe = __ldg(&((const int2*)idx)[E_EDGES / 4]);
    return probe.y == 0;
}

// ---------------------------------------------------------------------------
// K1: 8 edges per warp, 4 lanes per edge, 8 front-batched LDG.128 per thread
// (4 q-chunks + 4 k-chunks; each lane owns 64B of each half-row). MLP_p1 = 8.
// Lane 0 finishes all 8 edges: two float4 numerator stores, two int4 (or 4x
// longlong2) index loads, run-merged atomics. Grid exact, no bounds checks.
// ---------------------------------------------------------------------------
__global__ void __launch_bounds__(256)
score_exp_kernel(const float4* __restrict__ q,
                 const float4* __restrict__ k,
                 const void*   __restrict__ index,
                 float*        __restrict__ out) {
    const int tid  = blockIdx.x * blockDim.x + threadIdx.x;
    const int warp = tid >> 5;
    const int lane = tid & 31;
    const int g    = lane >> 2;       // edge within warp (0..7)
    const int sub  = lane & 3;        // lane within 4-group

    const long long base = ((long long)warp * 8 + g) * 16;  // float4 idx of row

    // Front-batched independent streaming loads (8 x LDG.128):
    const float4 q0 = __ldcs(&q[base + sub]);
    const float4 q1 = __ldcs(&q[base + sub + 4]);
    const float4 q2 = __ldcs(&q[base + sub + 8]);
    const float4 q3 = __ldcs(&q[base + sub + 12]);
    const float4 k0 = __ldcs(&k[base + sub]);
    const float4 k1 = __ldcs(&k[base + sub + 4]);
    const float4 k2 = __ldcs(&k[base + sub + 8]);
    const float4 k3 = __ldcs(&k[base + sub + 12]);

    float d = q0.x * k0.x + q0.y * k0.y + q0.z * k0.z + q0.w * k0.w;
    d += q1.x * k1.x + q1.y * k1.y + q1.z * k1.z + q1.w * k1.w;
    d += q2.x * k2.x + q2.y * k2.y + q2.z * k2.z + q2.w * k2.w;
    d += q3.x * k3.x + q3.y * k3.y + q3.z * k3.z + q3.w * k3.w;

    // Reduce within the 4-lane group (2 shuffles)
    d += __shfl_xor_sync(0xFFFFFFFFu, d, 2);
    d += __shfl_xor_sync(0xFFFFFFFFu, d, 1);

    // Every lane in group g now has edge g's score.
    const float ex = __expf(d * INV_TEMP);

    // Gather the 8 group results toward lane 0 (all lanes participate).
    const float e1 = __shfl_sync(0xFFFFFFFFu, ex, 4);
    const float e2 = __shfl_sync(0xFFFFFFFFu, ex, 8);
    const float e3 = __shfl_sync(0xFFFFFFFFu, ex, 12);
    const float e4 = __shfl_sync(0xFFFFFFFFu, ex, 16);
    const float e5 = __shfl_sync(0xFFFFFFFFu, ex, 20);
    const float e6 = __shfl_sync(0xFFFFFFFFu, ex, 24);
    const float e7 = __shfl_sync(0xFFFFFFFFu, ex, 28);

    if (lane == 0) {
        // Two 16B stores for 8 numerators (out + warp*8 is 32B-aligned).
        float4* ov = reinterpret_cast<float4*>(out) + warp * 2;
        __stcs(ov,     make_float4(ex, e1, e2, e3));
        __stcs(ov + 1, make_float4(e4, e5, e6, e7));

        // Vector loads for 8 segment ids.
        int s[8];
        if (index_is_64(index)) {
            const longlong2* ip = reinterpret_cast<const longlong2*>(index) + warp * 4;
            #pragma unroll
            for (int j = 0; j < 4; j++) {
                const longlong2 sv = __ldcs(ip + j);
                s[j * 2] = (int)sv.x; s[j * 2 + 1] = (int)sv.y;
            }
        } else {
            const int4* ip = reinterpret_cast<const int4*>(index) + warp * 2;
            const int4 sa = __ldcs(ip);
            const int4 sb = __ldcs(ip + 1);
            s[0] = sa.x; s[1] = sa.y; s[2] = sa.z; s[3] = sa.w;
            s[4] = sb.x; s[5] = sb.y; s[6] = sb.z; s[7] = sb.w;
        }

        const float ev[8] = {ex, e1, e2, e3, e4, e5, e6, e7};

        // Run-merge (index sorted -> typically ~1.4 REDG per 8 edges).
        float acc = ev[0];
        int   cur = s[0];
        #pragma unroll
        for (int j = 1; j < 8; j++) {
            if (s[j] == cur) {
                acc += ev[j];
            } else {
                atomicAdd(&g_sum[cur], acc);
                cur = s[j];
                acc = ev[j];
            }
        }
        atomicAdd(&g_sum[cur], acc);
    }
}

// ---------------------------------------------------------------------------
// K1.5: reciprocal of denominators + self-reset of g_sum for the next replay.
// ---------------------------------------------------------------------------
__global__ void __launch_bounds__(256)
rcp_kernel() {
    const int i = blockIdx.x * blockDim.x + threadIdx.x;  // 25000 threads
    if (i >= NSEG / 4) return;
    float4 s = reinterpret_cast<float4*>(g_sum)[i];
    float4 r;
    r.x = __fdividef(1.0f, s.x);
    r.y = __fdividef(1.0f, s.y);
    r.z = __fdividef(1.0f, s.z);
    r.w = __fdividef(1.0f, s.w);
    reinterpret_cast<float4*>(g_rcp)[i] = r;
    reinterpret_cast<float4*>(g_sum)[i] = make_float4(0.f, 0.f, 0.f, 0.f);
}

// ---------------------------------------------------------------------------
// K2: normalize = multiply by reciprocal. 4 edges/thread, vectorized.
// ---------------------------------------------------------------------------
__global__ void __launch_bounds__(256)
normalize_kernel(const void* __restrict__ index,
                 float*      __restrict__ out) {
    const int t = blockIdx.x * blockDim.x + threadIdx.x;
    const int i = t * 4;
    if (i >= E_EDGES) return;

    const bool is64 = index_is_64(index);

    float4 o = __ldcs(reinterpret_cast<const float4*>(out + i));

    int s0, s1, s2, s3;
    if (!is64) {
        const int4 sv = __ldcs(reinterpret_cast<const int4*>(index) + t);
        s0 = sv.x; s1 = sv.y; s2 = sv.z; s3 = sv.w;
    } else {
        const longlong2 sa = __ldcs(reinterpret_cast<const longlong2*>(index) + t * 2);
        const longlong2 sb = __ldcs(reinterpret_cast<const longlong2*>(index) + t * 2 + 1);
        s0 = (int)sa.x; s1 = (int)sa.y; s2 = (int)sb.x; s3 = (int)sb.y;
    }

    o.x *= __ldg(&g_rcp[s0]);
    o.y *= __ldg(&g_rcp[s1]);
    o.z *= __ldg(&g_rcp[s2]);
    o.w *= __ldg(&g_rcp[s3]);
    __stcs(reinterpret_cast<float4*>(out + i), o);
}

// ---------------------------------------------------------------------------
// Launch. Inputs in metadata order: q [E*64 f32], k [E*64 f32], index [E].
// Output: E f32. Three kernel nodes.
// ---------------------------------------------------------------------------
extern "C" void kernel_launch(void* const* d_in, const int* in_sizes, int n_in,
                              void* d_out, int out_size) {
    const float4* q   = (const float4*)d_in[0];
    const float4* k   = (const float4*)d_in[1];
    const void*   idx = d_in[2];
    float*        out = (float*)d_out;

    // K1: 8 edges per warp -> E*4 threads (divides 256 exactly: 31250 blocks)
    {
        const long long total_threads = (long long)E_EDGES * 4;
        const int blocks = (int)(total_threads / 256);
        score_exp_kernel<<<blocks, 256>>>(q, k, idx, out);
    }

    // K1.5: reciprocals + reset (25000 threads)
    rcp_kernel<<<(NSEG / 4 + 255) / 256, 256>>>();

    // K2: 4 edges per thread
    {
        const int threads = E_EDGES / 4;
        normalize_kernel<<<(threads + 255) / 256, 256>>>(idx, out);
    }
}

// round 6
// speedup vs baseline: 1.0090x; 1.0090x over previous
#include <cuda_runtime.h>

// Problem constants (fixed by the reference)
#define E_EDGES   2000000
#define NSEG      100000
#define INV_TEMP  0.125f   // 1 / TEMPERATURE

// Scratch (no allocs allowed): denominators + reciprocals.
// g_sum is zero-initialized at module load; rcp_kernel re-zeroes it every
// call, so each kernel_launch sees zeros -> deterministic across replays.
__device__ float g_sum[NSEG];
__device__ float g_rcp[NSEG];

// ---------------------------------------------------------------------------
// Index dtype detection: reference asks int64 but default JAX canonicalizes to
// int32. Probe 8 bytes at int64-position E/4: sorted uniform over [0,100000)
// -> int64 hi-word there is 0; int32 interpretation puts ~50000 there.
// ---------------------------------------------------------------------------
__device__ __forceinline__ bool index_is_64(const void* __restrict__ idx) {
    const int2 probe = __ldg(&((const int2*)idx)[E_EDGES / 4]);
    return probe.y == 0;
}

// ---------------------------------------------------------------------------
// K1 (R4 winner, unchanged): 4 edges per warp, 8 lanes per edge, 4
// front-batched LDG.128 per thread. regs=26, occ ~90%, DRAM ~87.5%.
// ---------------------------------------------------------------------------
__global__ void __launch_bounds__(256)
score_exp_kernel(const float4* __restrict__ q,
                 const float4* __restrict__ k,
                 const void*   __restrict__ index,
                 float*        __restrict__ out) {
    const int tid  = blockIdx.x * blockDim.x + threadIdx.x;
    const int warp = tid >> 5;
    const int lane = tid & 31;
    const int g    = lane >> 3;       // edge within warp (0..3)
    const int sub  = lane & 7;        // lane within 8-group

    const long long e    = (long long)warp * 4 + g;
    const long long base = e * 16;    // float4 index of row start

    // Front-batched independent streaming loads (MLP_p1 = 4):
    const float4 qa = __ldcs(&q[base + sub]);
    const float4 qb = __ldcs(&q[base + sub + 8]);
    const float4 ka = __ldcs(&k[base + sub]);
    const float4 kb = __ldcs(&k[base + sub + 8]);

    float d0 = qa.x * ka.x + qa.y * ka.y + qa.z * ka.z + qa.w * ka.w;
    float d1 = qb.x * kb.x + qb.y * kb.y + qb.z * kb.z + qb.w * kb.w;
    float d  = d0 + d1;

    // Reduce within the 8-lane group (3 shuffles)
    d += __shfl_xor_sync(0xFFFFFFFFu, d, 4);
    d += __shfl_xor_sync(0xFFFFFFFFu, d, 2);
    d += __shfl_xor_sync(0xFFFFFFFFu, d, 1);

    // Every lane in group g now has edge g's score; exponentiate (MUFU).
    const float ex = __expf(d * INV_TEMP);

    // Gather the 4 group results to lane 0.
    const float e1 = __shfl_sync(0xFFFFFFFFu, ex, 8);
    const float e2 = __shfl_sync(0xFFFFFFFFu, ex, 16);
    const float e3 = __shfl_sync(0xFFFFFFFFu, ex, 24);

    if (lane == 0) {
        // One 16B store for 4 numerators (out + warp*4 is 16B-aligned).
        __stcs(reinterpret_cast<float4*>(out) + warp, make_float4(ex, e1, e2, e3));

        // One vector load for 4 segment ids.
        int s0, s1, s2, s3;
        if (index_is_64(index)) {
            const longlong2 sa = __ldcs(reinterpret_cast<const longlong2*>(index) + warp * 2);
            const longlong2 sb = __ldcs(reinterpret_cast<const longlong2*>(index) + warp * 2 + 1);
            s0 = (int)sa.x; s1 = (int)sa.y; s2 = (int)sb.x; s3 = (int)sb.y;
        } else {
            const int4 sv = __ldcs(reinterpret_cast<const int4*>(index) + warp);
            s0 = sv.x; s1 = sv.y; s2 = sv.z; s3 = sv.w;
        }

        // Run-merge (index sorted -> usually one REDG per 4 edges).
        float acc = ex;
        int   cur = s0;
        if (s1 == cur) acc += e1; else { atomicAdd(&g_sum[cur], acc); cur = s1; acc = e1; }
        if (s2 == cur) acc += e2; else { atomicAdd(&g_sum[cur], acc); cur = s2; acc = e2; }
        if (s3 == cur) acc += e3; else { atomicAdd(&g_sum[cur], acc); cur = s3; acc = e3; }
        atomicAdd(&g_sum[cur], acc);
    }
}

// ---------------------------------------------------------------------------
// K1.5: reciprocal of denominators + self-reset of g_sum for the next replay.
// 8 segments/thread -> 12500 threads, 49 blocks, single wave.
// ---------------------------------------------------------------------------
__global__ void __launch_bounds__(256)
rcp_kernel() {
    const int i = blockIdx.x * blockDim.x + threadIdx.x;  // 12500 threads
    if (i >= NSEG / 8) return;
    float4 sa = reinterpret_cast<float4*>(g_sum)[i * 2];
    float4 sb = reinterpret_cast<float4*>(g_sum)[i * 2 + 1];
    float4 ra, rb;
    ra.x = __fdividef(1.0f, sa.x);
    ra.y = __fdividef(1.0f, sa.y);
    ra.z = __fdividef(1.0f, sa.z);
    ra.w = __fdividef(1.0f, sa.w);
    rb.x = __fdividef(1.0f, sb.x);
    rb.y = __fdividef(1.0f, sb.y);
    rb.z = __fdividef(1.0f, sb.z);
    rb.w = __fdividef(1.0f, sb.w);
    reinterpret_cast<float4*>(g_rcp)[i * 2]     = ra;
    reinterpret_cast<float4*>(g_rcp)[i * 2 + 1] = rb;
    const float4 z = make_float4(0.f, 0.f, 0.f, 0.f);
    reinterpret_cast<float4*>(g_sum)[i * 2]     = z;
    reinterpret_cast<float4*>(g_sum)[i * 2 + 1] = z;
}

// ---------------------------------------------------------------------------
// K2: normalize = multiply by reciprocal. 8 edges/thread, all streaming loads
// front-batched before the dependent g_rcp gathers (latency-bound kernel ->
// maximize per-thread MLP). E/8 = 250000 threads, 977 blocks.
// ---------------------------------------------------------------------------
__global__ void __launch_bounds__(256)
normalize_kernel(const void* __restrict__ index,
                 float*      __restrict__ out) {
    const int t = blockIdx.x * blockDim.x + threadIdx.x;
    if (t >= E_EDGES / 8) return;

    const bool is64 = index_is_64(index);

    // Front-batched: two out vectors + index vectors.
    float4* ov = reinterpret_cast<float4*>(out) + t * 2;
    float4 o0 = __ldcs(ov);
    float4 o1 = __ldcs(ov + 1);

    int s[8];
    if (!is64) {
        const int4* ip = reinterpret_cast<const int4*>(index) + t * 2;
        const int4 a = __ldcs(ip);
        const int4 b = __ldcs(ip + 1);
        s[0] = a.x; s[1] = a.y; s[2] = a.z; s[3] = a.w;
        s[4] = b.x; s[5] = b.y; s[6] = b.z; s[7] = b.w;
    } else {
        const longlong2* ip = reinterpret_cast<const longlong2*>(index) + t * 4;
        #pragma unroll
        for (int j = 0; j < 4; j++) {
            const longlong2 sv = __ldcs(ip + j);
            s[j * 2] = (int)sv.x; s[j * 2 + 1] = (int)sv.y;
        }
    }

    // 8 independent gathers (sorted index -> L1/L2 hits, usually same line).
    float r0 = __ldg(&g_rcp[s[0]]);
    float r1 = __ldg(&g_rcp[s[1]]);
    float r2 = __ldg(&g_rcp[s[2]]);
    float r3 = __ldg(&g_rcp[s[3]]);
    float r4 = __ldg(&g_rcp[s[4]]);
    float r5 = __ldg(&g_rcp[s[5]]);
    float r6 = __ldg(&g_rcp[s[6]]);
    float r7 = __ldg(&g_rcp[s[7]]);

    o0.x *= r0; o0.y *= r1; o0.z *= r2; o0.w *= r3;
    o1.x *= r4; o1.y *= r5; o1.z *= r6; o1.w *= r7;
    __stcs(ov,     o0);
    __stcs(ov + 1, o1);
}

// ---------------------------------------------------------------------------
// Launch. Inputs in metadata order: q [E*64 f32], k [E*64 f32], index [E].
// Output: E f32. Three kernel nodes.
// ---------------------------------------------------------------------------
extern "C" void kernel_launch(void* const* d_in, const int* in_sizes, int n_in,
                              void* d_out, int out_size) {
    const float4* q   = (const float4*)d_in[0];
    const float4* k   = (const float4*)d_in[1];
    const void*   idx = d_in[2];
    float*        out = (float*)d_out;

    // K1: 4 edges per warp -> E*8 threads (divides 256 exactly: 62500 blocks)
    {
        const long long total_threads = (long long)E_EDGES * 8;
        const int blocks = (int)(total_threads / 256);
        score_exp_kernel<<<blocks, 256>>>(q, k, idx, out);
    }

    // K1.5: reciprocals + reset (12500 threads, 49 blocks)
    rcp_kernel<<<(NSEG / 8 + 255) / 256, 256>>>();

    // K2: 8 edges per thread (250000 threads, 977 blocks)
    {
        const int threads = E_EDGES / 8;
        normalize_kernel<<<(threads + 255) / 256, 256>>>(idx, out);
    }
}

// round 7
// speedup vs baseline: 1.0469x; 1.0376x over previous
#include <cuda_runtime.h>

// Problem constants (fixed by the reference)
#define E_EDGES   2000000
#define NSEG      100000
#define INV_TEMP  0.125f   // 1 / TEMPERATURE

// Scratch (no allocs allowed): denominators + reciprocals.
// g_sum is zero-initialized at module load; rcp_kernel re-zeroes it every
// call, so each kernel_launch sees zeros -> deterministic across replays.
__device__ float g_sum[NSEG];
__device__ float g_rcp[NSEG];

// ---------------------------------------------------------------------------
// Index dtype detection: reference asks int64 but default JAX canonicalizes to
// int32. Probe 8 bytes at int64-position E/4: sorted uniform over [0,100000)
// -> int64 hi-word there is 0; int32 interpretation puts ~50000 there.
// ---------------------------------------------------------------------------
__device__ __forceinline__ bool index_is_64(const void* __restrict__ idx) {
    const int2 probe = __ldg(&((const int2*)idx)[E_EDGES / 4]);
    return probe.y == 0;
}

// ---------------------------------------------------------------------------
// K1 (R4 winner): 4 edges per warp, 8 lanes per edge, 4 front-batched LDG.128
// per thread (MLP_p1=4, regs 26, occ ~90%, DRAM ~88%).
// Policy change vs R4: out stored with __stcg and index read with __ldg so
// both stay L2-resident (L2 = 126 MB) for K2's re-read; q/k stay streaming.
// ---------------------------------------------------------------------------
__global__ void __launch_bounds__(256)
score_exp_kernel(const float4* __restrict__ q,
                 const float4* __restrict__ k,
                 const void*   __restrict__ index,
                 float*        __restrict__ out) {
    const int tid  = blockIdx.x * blockDim.x + threadIdx.x;
    const int warp = tid >> 5;
    const int lane = tid & 31;
    const int g    = lane >> 3;       // edge within warp (0..3)
    const int sub  = lane & 7;        // lane within 8-group

    const long long e    = (long long)warp * 4 + g;
    const long long base = e * 16;    // float4 index of row start

    // Front-batched independent streaming loads (MLP_p1 = 4):
    const float4 qa = __ldcs(&q[base + sub]);
    const float4 qb = __ldcs(&q[base + sub + 8]);
    const float4 ka = __ldcs(&k[base + sub]);
    const float4 kb = __ldcs(&k[base + sub + 8]);

    float d0 = qa.x * ka.x + qa.y * ka.y + qa.z * ka.z + qa.w * ka.w;
    float d1 = qb.x * kb.x + qb.y * kb.y + qb.z * kb.z + qb.w * kb.w;
    float d  = d0 + d1;

    // Reduce within the 8-lane group (3 shuffles)
    d += __shfl_xor_sync(0xFFFFFFFFu, d, 4);
    d += __shfl_xor_sync(0xFFFFFFFFu, d, 2);
    d += __shfl_xor_sync(0xFFFFFFFFu, d, 1);

    // Every lane in group g now has edge g's score; exponentiate (MUFU).
    const float ex = __expf(d * INV_TEMP);

    // Gather the 4 group results to lane 0.
    const float e1 = __shfl_sync(0xFFFFFFFFu, ex, 8);
    const float e2 = __shfl_sync(0xFFFFFFFFu, ex, 16);
    const float e3 = __shfl_sync(0xFFFFFFFFu, ex, 24);

    if (lane == 0) {
        // One 16B store for 4 numerators; evict-normal -> stays in L2 for K2.
        __stcg(reinterpret_cast<float4*>(out) + warp, make_float4(ex, e1, e2, e3));

        // One vector load for 4 segment ids; cached -> L2-resident for K2.
        int s0, s1, s2, s3;
        if (index_is_64(index)) {
            const longlong2 sa = __ldg(reinterpret_cast<const longlong2*>(index) + warp * 2);
            const longlong2 sb = __ldg(reinterpret_cast<const longlong2*>(index) + warp * 2 + 1);
            s0 = (int)sa.x; s1 = (int)sa.y; s2 = (int)sb.x; s3 = (int)sb.y;
        } else {
            const int4 sv = __ldg(reinterpret_cast<const int4*>(index) + warp);
            s0 = sv.x; s1 = sv.y; s2 = sv.z; s3 = sv.w;
        }

        // Run-merge (index sorted -> usually one REDG per 4 edges).
        float acc = ex;
        int   cur = s0;
        if (s1 == cur) acc += e1; else { atomicAdd(&g_sum[cur], acc); cur = s1; acc = e1; }
        if (s2 == cur) acc += e2; else { atomicAdd(&g_sum[cur], acc); cur = s2; acc = e2; }
        if (s3 == cur) acc += e3; else { atomicAdd(&g_sum[cur], acc); cur = s3; acc = e3; }
        atomicAdd(&g_sum[cur], acc);
    }
}

// ---------------------------------------------------------------------------
// K1.5: reciprocal of denominators + self-reset of g_sum for the next replay.
// 8 segments/thread -> 12500 threads, 49 blocks, single wave.
// ---------------------------------------------------------------------------
__global__ void __launch_bounds__(256)
rcp_kernel() {
    const int i = blockIdx.x * blockDim.x + threadIdx.x;
    if (i >= NSEG / 8) return;
    float4 sa = reinterpret_cast<float4*>(g_sum)[i * 2];
    float4 sb = reinterpret_cast<float4*>(g_sum)[i * 2 + 1];
    float4 ra, rb;
    ra.x = __fdividef(1.0f, sa.x);
    ra.y = __fdividef(1.0f, sa.y);
    ra.z = __fdividef(1.0f, sa.z);
    ra.w = __fdividef(1.0f, sa.w);
    rb.x = __fdividef(1.0f, sb.x);
    rb.y = __fdividef(1.0f, sb.y);
    rb.z = __fdividef(1.0f, sb.z);
    rb.w = __fdividef(1.0f, sb.w);
    reinterpret_cast<float4*>(g_rcp)[i * 2]     = ra;
    reinterpret_cast<float4*>(g_rcp)[i * 2 + 1] = rb;
    const float4 z = make_float4(0.f, 0.f, 0.f, 0.f);
    reinterpret_cast<float4*>(g_sum)[i * 2]     = z;
    reinterpret_cast<float4*>(g_sum)[i * 2 + 1] = z;
}

// ---------------------------------------------------------------------------
// K2 (R4 shape): normalize = multiply by reciprocal. 4 edges/thread,
// 1954 blocks. out/index now L2-resident from K1 -> loads are L2 hits.
// ---------------------------------------------------------------------------
__global__ void __launch_bounds__(256)
normalize_kernel(const void* __restrict__ index,
                 float*      __restrict__ out) {
    const int t = blockIdx.x * blockDim.x + threadIdx.x;
    const int i = t * 4;
    if (i >= E_EDGES) return;

    const bool is64 = index_is_64(index);

    float4 o = __ldg(reinterpret_cast<const float4*>(out) + t);

    int s0, s1, s2, s3;
    if (!is64) {
        const int4 sv = __ldg(reinterpret_cast<const int4*>(index) + t);
        s0 = sv.x; s1 = sv.y; s2 = sv.z; s3 = sv.w;
    } else {
        const longlong2 sa = __ldg(reinterpret_cast<const longlong2*>(index) + t * 2);
        const longlong2 sb = __ldg(reinterpret_cast<const longlong2*>(index) + t * 2 + 1);
        s0 = (int)sa.x; s1 = (int)sa.y; s2 = (int)sb.x; s3 = (int)sb.y;
    }

    o.x *= __ldg(&g_rcp[s0]);
    o.y *= __ldg(&g_rcp[s1]);
    o.z *= __ldg(&g_rcp[s2]);
    o.w *= __ldg(&g_rcp[s3]);
    __stcs(reinterpret_cast<float4*>(out) + t, o);
}

// ---------------------------------------------------------------------------
// Launch. Inputs in metadata order: q [E*64 f32], k [E*64 f32], index [E].
// Output: E f32. Three kernel nodes.
// ---------------------------------------------------------------------------
extern "C" void kernel_launch(void* const* d_in, const int* in_sizes, int n_in,
                              void* d_out, int out_size) {
    const float4* q   = (const float4*)d_in[0];
    const float4* k   = (const float4*)d_in[1];
    const void*   idx = d_in[2];
    float*        out = (float*)d_out;

    // K1: 4 edges per warp -> E*8 threads (62500 blocks)
    {
        const long long total_threads = (long long)E_EDGES * 8;
        const int blocks = (int)(total_threads / 256);
        score_exp_kernel<<<blocks, 256>>>(q, k, idx, out);
    }

    // K1.5: reciprocals + reset (12500 threads, 49 blocks)
    rcp_kernel<<<(NSEG / 8 + 255) / 256, 256>>>();

    // K2: 4 edges per thread (500000 threads, 1954 blocks)
    {
        const int threads = E_EDGES / 4;
        normalize_kernel<<<(threads + 255) / 256, 256>>>(idx, out);
    }
}